// round 7
// baseline (speedup 1.0000x reference)
#include <cuda_runtime.h>
#include <cuda_bf16.h>
#include <cstdint>

// Problem dims
#define Bb 16384
#define Dd 1024
#define Hh 1024
#define Nn 4096   // 4*H
#define Kk 2048   // D + H

// GEMM tiling
#define BM 128
#define BN 128
#define BK 32
#define STAGES 3
#define SMEM_STAGE (BM * BK)                       // floats per operand per stage
#define GEMM_SMEM_BYTES (STAGES * 2 * SMEM_STAGE * 4)   // 98304 bytes

// Scratch (device globals — allocation-free per harness rules)
__device__ float g_A[(size_t)Bb * Kk];     // 128 MB: [x | h], tf32-rounded
__device__ float g_W[(size_t)Nn * Kk];     //  32 MB: [Wi | Wh], tf32-rounded
__device__ float g_pre[(size_t)Bb * Nn];   // 256 MB: pre-activations

__device__ __forceinline__ float rna_tf32(float v) {
    uint32_t u;
    asm("cvt.rna.tf32.f32 %0, %1;" : "=r"(u) : "f"(v));
    return __uint_as_float(u);
}

// ---------------------------------------------------------------------------
// Pack kernels: concatenate along K and round to tf32 once (so the GEMM
// mainloop has zero cvt instructions).
// ---------------------------------------------------------------------------
__global__ void pack_A(const float* __restrict__ x, const float* __restrict__ h) {
    size_t i = (size_t)blockIdx.x * blockDim.x + threadIdx.x;  // one float4
    size_t b = i >> 9;            // 2048/4 = 512 float4 per row
    int k4 = (int)(i & 511);
    float4 v = (k4 < 256) ? reinterpret_cast<const float4*>(x + b * 1024)[k4]
                          : reinterpret_cast<const float4*>(h + b * 1024)[k4 - 256];
    float4 o;
    o.x = rna_tf32(v.x); o.y = rna_tf32(v.y);
    o.z = rna_tf32(v.z); o.w = rna_tf32(v.w);
    reinterpret_cast<float4*>(g_A)[i] = o;
}

__global__ void pack_W(const float* __restrict__ Wi, const float* __restrict__ Wh) {
    size_t i = (size_t)blockIdx.x * blockDim.x + threadIdx.x;
    size_t n = i >> 9;            // row n = gate*1024 + h  (Wi flattens to [4096,1024])
    int k4 = (int)(i & 511);
    float4 v = (k4 < 256) ? reinterpret_cast<const float4*>(Wi + n * 1024)[k4]
                          : reinterpret_cast<const float4*>(Wh + n * 1024)[k4 - 256];
    float4 o;
    o.x = rna_tf32(v.x); o.y = rna_tf32(v.y);
    o.z = rna_tf32(v.z); o.w = rna_tf32(v.w);
    reinterpret_cast<float4*>(g_W)[i] = o;
}

// ---------------------------------------------------------------------------
// TF32 tensor-core GEMM: g_pre = g_A (16384x2048) * g_W^T (2048x4096)
// ---------------------------------------------------------------------------
__device__ __forceinline__ int swz(int r, int c) {
    // XOR swizzle: conflict-free for both the 16B cp.async stores and the
    // m16n8k8 fragment loads (8 rows x {c, c+4} per warp).
    return r * BK + (c ^ ((r & 7) << 2));
}

__device__ __forceinline__ void cp16(float* s, const float* g) {
    uint32_t sa = (uint32_t)__cvta_generic_to_shared(s);
    asm volatile("cp.async.cg.shared.global [%0], [%1], 16;" :: "r"(sa), "l"(g));
}
__device__ __forceinline__ void cp_commit() {
    asm volatile("cp.async.commit_group;");
}
template <int N>
__device__ __forceinline__ void cp_wait() {
    asm volatile("cp.async.wait_group %0;" :: "n"(N));
}

__global__ void __launch_bounds__(256, 2) gemm_tf32() {
    extern __shared__ float smem[];
    float* As = smem;
    float* Bs = smem + STAGES * SMEM_STAGE;

    // Band-ordered tile schedule: 16 M-tiles per band, sweep all 32 N-tiles.
    // Keeps W (32MB) + one A band (16MB) resident in L2.
    int bid = blockIdx.x;
    int band = bid >> 9;                 // /512
    int within = bid & 511;
    int mtile = band * 16 + (within & 15);
    int ntile = within >> 4;

    int tid = threadIdx.x;
    int lane = tid & 31, warp = tid >> 5;
    int wm = warp & 3, wn = warp >> 2;   // 4 x 2 warp grid, warp tile 32x64

    const float* gA = g_A + (size_t)mtile * BM * Kk;
    const float* gB = g_W + (size_t)ntile * BN * Kk;

    float acc[2][8][4];
#pragma unroll
    for (int i = 0; i < 2; i++)
#pragma unroll
        for (int j = 0; j < 8; j++)
#pragma unroll
            for (int l = 0; l < 4; l++) acc[i][j][l] = 0.f;

    auto load_stage = [&](int s, int kt) {
        float* as = As + s * SMEM_STAGE;
        float* bs = Bs + s * SMEM_STAGE;
#pragma unroll
        for (int i = 0; i < 4; i++) {
            int c = tid + i * 256;           // 1024 chunks of 16B per operand
            int row = c >> 3, kc = c & 7;
            cp16(as + swz(row, kc * 4), gA + (size_t)row * Kk + kt * BK + kc * 4);
            cp16(bs + swz(row, kc * 4), gB + (size_t)row * Kk + kt * BK + kc * 4);
        }
    };

    const int KT = Kk / BK;  // 64
    load_stage(0, 0); cp_commit();
    load_stage(1, 1); cp_commit();

    int rq = lane >> 2, cq = lane & 3;

    for (int kt = 0; kt < KT; kt++) {
        cp_wait<STAGES - 2>();
        __syncthreads();

        int pf = kt + STAGES - 1;
        if (pf < KT) load_stage(pf % STAGES, pf);
        cp_commit();

        const float* as = As + (kt % STAGES) * SMEM_STAGE;
        const float* bs = Bs + (kt % STAGES) * SMEM_STAGE;

#pragma unroll
        for (int k8 = 0; k8 < 4; k8++) {
            uint32_t a[2][4], b[8][2];
            int k0 = k8 * 8 + cq;
#pragma unroll
            for (int mi = 0; mi < 2; mi++) {
                int r = wm * 32 + mi * 16 + rq;
                a[mi][0] = __float_as_uint(as[swz(r,     k0)]);
                a[mi][1] = __float_as_uint(as[swz(r + 8, k0)]);
                a[mi][2] = __float_as_uint(as[swz(r,     k0 + 4)]);
                a[mi][3] = __float_as_uint(as[swz(r + 8, k0 + 4)]);
            }
#pragma unroll
            for (int ni = 0; ni < 8; ni++) {
                int rn = wn * 64 + ni * 8 + rq;
                b[ni][0] = __float_as_uint(bs[swz(rn, k0)]);
                b[ni][1] = __float_as_uint(bs[swz(rn, k0 + 4)]);
            }
#pragma unroll
            for (int mi = 0; mi < 2; mi++)
#pragma unroll
                for (int ni = 0; ni < 8; ni++) {
                    float* c = acc[mi][ni];
                    asm volatile(
                        "mma.sync.aligned.m16n8k8.row.col.f32.tf32.tf32.f32 "
                        "{%0,%1,%2,%3}, {%4,%5,%6,%7}, {%8,%9}, {%0,%1,%2,%3};"
                        : "+f"(c[0]), "+f"(c[1]), "+f"(c[2]), "+f"(c[3])
                        : "r"(a[mi][0]), "r"(a[mi][1]), "r"(a[mi][2]), "r"(a[mi][3]),
                          "r"(b[ni][0]), "r"(b[ni][1]));
                }
        }
    }

    // Epilogue: store fp32 pre-activations
    size_t baseM = (size_t)mtile * BM + wm * 32;
    size_t baseN = (size_t)ntile * BN + wn * 64;
#pragma unroll
    for (int mi = 0; mi < 2; mi++)
#pragma unroll
        for (int ni = 0; ni < 8; ni++) {
            size_t r = baseM + mi * 16 + rq;
            size_t cc = baseN + ni * 8 + cq * 2;
            float2 v0 = make_float2(acc[mi][ni][0], acc[mi][ni][1]);
            float2 v1 = make_float2(acc[mi][ni][2], acc[mi][ni][3]);
            *reinterpret_cast<float2*>(g_pre + r * Nn + cc) = v0;
            *reinterpret_cast<float2*>(g_pre + (r + 8) * Nn + cc) = v1;
        }
}

// ---------------------------------------------------------------------------
// Elementwise LSTM gate update
// ---------------------------------------------------------------------------
__global__ void lstm_elem(const float* __restrict__ c, const float* __restrict__ bi,
                          float* __restrict__ out, int out_size) {
    int idx = blockIdx.x * blockDim.x + threadIdx.x;
    int b = idx >> 10, h = idx & 1023;
    const float* p = g_pre + (size_t)b * Nn;

    float pi = p[h]          + bi[h];
    float pf = p[1024 + h]   + bi[1024 + h];
    float pg = p[2048 + h]   + bi[2048 + h];
    float po = p[3072 + h]   + bi[3072 + h];

    float gi = 1.f / (1.f + expf(-pi));
    float gf = 1.f / (1.f + expf(-pf));
    float gg = tanhf(pg);
    float go = 1.f / (1.f + expf(-po));

    float cv = c[idx];
    float nc = gf * cv + gi * gg;
    float nh = go * tanhf(nc);

    out[idx] = go;
    if (out_size >= 3 * Bb * Hh) {
        out[(size_t)Bb * Hh + idx]     = nh;
        out[(size_t)2 * Bb * Hh + idx] = nc;
    }
}

// ---------------------------------------------------------------------------
// Launch: pack -> GEMM -> elementwise (default stream, graph-capturable)
// ---------------------------------------------------------------------------
extern "C" void kernel_launch(void* const* d_in, const int* in_sizes, int n_in,
                              void* d_out, int out_size) {
    const float* x  = (const float*)d_in[0];
    const float* h  = (const float*)d_in[1];
    const float* c  = (const float*)d_in[2];
    const float* Wi = (const float*)d_in[3];
    const float* bi = (const float*)d_in[4];
    const float* Wh = (const float*)d_in[5];
    float* out = (float*)d_out;

    pack_A<<<(Bb * 512) / 256, 256>>>(x, h);      // 32768 blocks
    pack_W<<<(Nn * 512) / 256, 256>>>(Wi, Wh);    //  8192 blocks

    cudaFuncSetAttribute(gemm_tf32, cudaFuncAttributeMaxDynamicSharedMemorySize,
                         GEMM_SMEM_BYTES);
    gemm_tf32<<<(Bb / BM) * (Nn / BN), 256, GEMM_SMEM_BYTES>>>();  // 4096 CTAs

    lstm_elem<<<(Bb * Hh) / 256, 256>>>(c, bi, out, out_size);
}

// round 10
// speedup vs baseline: 1.7520x; 1.7520x over previous
#include <cuda_runtime.h>
#include <cstdint>

// Problem dims
#define Bb 16384
#define Hh 1024
#define Nn 4096   // 4*H
#define Kk 2048   // D + H

// GEMM tiling: CTA 128x256x32, 8 warps, warp tile 64x64
#define BM 128
#define BN 256
#define BK 32
#define KT (Kk / BK)        // 64
#define STAGES 4
#define A_FLOATS (BM * BK)              // 4096
#define B_FLOATS (BN * BK)              // 8192
#define STAGE_FLOATS (A_FLOATS + B_FLOATS)   // 12288
#define GEMM_SMEM_BYTES (STAGES * STAGE_FLOATS * 4)  // 196608 = 192KB

// Scratch (device globals — allocation-free per harness rules)
__device__ float g_A[(size_t)Bb * Kk];     // [x | h], tf32-rounded, K-major
__device__ float g_W[(size_t)Nn * Kk];     // [Wi | Wh], tf32-rounded, K-major
__device__ float g_pre[(size_t)Bb * Nn];   // pre-activations

__device__ __forceinline__ float rna_tf32(float v) {
    uint32_t u; asm("cvt.rna.tf32.f32 %0, %1;" : "=r"(u) : "f"(v));
    return __uint_as_float(u);
}

// ---------------------------------------------------------------------------
// Pack kernels: concatenate along K and round to tf32 once.
// ---------------------------------------------------------------------------
__global__ void pack_A(const float* __restrict__ x, const float* __restrict__ h) {
    size_t i = (size_t)blockIdx.x * blockDim.x + threadIdx.x;
    size_t b = i >> 9;
    int k4 = (int)(i & 511);
    float4 v = (k4 < 256) ? reinterpret_cast<const float4*>(x + b * 1024)[k4]
                          : reinterpret_cast<const float4*>(h + b * 1024)[k4 - 256];
    float4 o;
    o.x = rna_tf32(v.x); o.y = rna_tf32(v.y); o.z = rna_tf32(v.z); o.w = rna_tf32(v.w);
    reinterpret_cast<float4*>(g_A)[i] = o;
}
__global__ void pack_W(const float* __restrict__ Wi, const float* __restrict__ Wh) {
    size_t i = (size_t)blockIdx.x * blockDim.x + threadIdx.x;
    size_t n = i >> 9;
    int k4 = (int)(i & 511);
    float4 v = (k4 < 256) ? reinterpret_cast<const float4*>(Wi + n * 1024)[k4]
                          : reinterpret_cast<const float4*>(Wh + n * 1024)[k4 - 256];
    float4 o;
    o.x = rna_tf32(v.x); o.y = rna_tf32(v.y); o.z = rna_tf32(v.z); o.w = rna_tf32(v.w);
    reinterpret_cast<float4*>(g_W)[i] = o;
}

// ---------------------------------------------------------------------------
// TF32 mma.sync GEMM: g_pre = g_A (16384x2048) * g_W^T (2048x4096)
// ---------------------------------------------------------------------------
__device__ __forceinline__ int swz(int r, int c) {
    // XOR swizzle: conflict-free for the 16B cp.async stores and the
    // m16n8k8 fragment loads (verified: bank = (c ^ ((r&7)<<2)) & 31,
    // distinct across the 8x4 (rq,cq) lane grid).
    return r * BK + (c ^ ((r & 7) << 2));
}
__device__ __forceinline__ void cp16(uint32_t s, const float* g) {
    asm volatile("cp.async.cg.shared.global [%0], [%1], 16;" :: "r"(s), "l"(g));
}
__device__ __forceinline__ void cp_commit() { asm volatile("cp.async.commit_group;"); }
template <int N>
__device__ __forceinline__ void cp_wait() { asm volatile("cp.async.wait_group %0;" :: "n"(N)); }

__global__ void __launch_bounds__(256, 1) gemm_tf32() {
    extern __shared__ float smem[];
    uint32_t smem_u;
    asm("{ .reg .u64 t; cvta.to.shared.u64 t, %1; cvt.u32.u64 %0, t; }"
        : "=r"(smem_u) : "l"(smem));

    // Band schedule: ntile inner -> one wave shares A band + all of W in L2.
    int bid = blockIdx.x;
    int ntile = bid & 15;     // 16 n-tiles of 256
    int mtile = bid >> 4;     // 128 m-tiles of 128

    int tid = threadIdx.x;
    int lane = tid & 31, warp = tid >> 5;
    int wm = warp & 1, wn = warp >> 1;    // 2 x 4 warp grid, warp tile 64x64
    int rq = lane >> 2, cq = lane & 3;

    const float* gA = g_A + (size_t)mtile * BM * Kk;
    const float* gB = g_W + (size_t)ntile * BN * Kk;

    float acc[4][8][4];
#pragma unroll
    for (int i = 0; i < 4; i++)
#pragma unroll
        for (int j = 0; j < 8; j++)
#pragma unroll
            for (int l = 0; l < 4; l++) acc[i][j][l] = 0.f;

    auto load_stage = [&](int s, int kt) {
        uint32_t as = smem_u + (uint32_t)(s * STAGE_FLOATS) * 4;
        uint32_t bs = as + A_FLOATS * 4;
        // A: 1024 16B chunks (128 rows x 8)
#pragma unroll
        for (int i = 0; i < 4; i++) {
            int ch = i * 256 + tid;
            int row = ch >> 3, c = ch & 7;
            cp16(as + (uint32_t)swz(row, c * 4) * 4,
                 gA + (size_t)row * Kk + kt * BK + c * 4);
        }
        // B: 2048 16B chunks (256 rows x 8)
#pragma unroll
        for (int i = 0; i < 8; i++) {
            int ch = i * 256 + tid;
            int row = ch >> 3, c = ch & 7;
            cp16(bs + (uint32_t)swz(row, c * 4) * 4,
                 gB + (size_t)row * Kk + kt * BK + c * 4);
        }
    };

#pragma unroll
    for (int s = 0; s < STAGES - 1; s++) { load_stage(s, s); cp_commit(); }

    for (int kt = 0; kt < KT; kt++) {
        cp_wait<STAGES - 2>();
        __syncthreads();

        int pf = kt + STAGES - 1;
        if (pf < KT) load_stage(pf & (STAGES - 1), pf);
        cp_commit();

        const float* as = smem + (kt & (STAGES - 1)) * STAGE_FLOATS;
        const float* bs = as + A_FLOATS;

#pragma unroll
        for (int k8 = 0; k8 < 4; k8++) {
            int k0 = k8 * 8 + cq;
            uint32_t a[4][4], b[8][2];
#pragma unroll
            for (int mi = 0; mi < 4; mi++) {
                int r = wm * 64 + mi * 16 + rq;
                a[mi][0] = __float_as_uint(as[swz(r,     k0)]);
                a[mi][1] = __float_as_uint(as[swz(r + 8, k0)]);
                a[mi][2] = __float_as_uint(as[swz(r,     k0 + 4)]);
                a[mi][3] = __float_as_uint(as[swz(r + 8, k0 + 4)]);
            }
#pragma unroll
            for (int ni = 0; ni < 8; ni++) {
                int rn = wn * 64 + ni * 8 + rq;
                b[ni][0] = __float_as_uint(bs[swz(rn, k0)]);
                b[ni][1] = __float_as_uint(bs[swz(rn, k0 + 4)]);
            }
#pragma unroll
            for (int mi = 0; mi < 4; mi++)
#pragma unroll
                for (int ni = 0; ni < 8; ni++) {
                    float* c = acc[mi][ni];
                    asm volatile(
                        "mma.sync.aligned.m16n8k8.row.col.f32.tf32.tf32.f32 "
                        "{%0,%1,%2,%3}, {%4,%5,%6,%7}, {%8,%9}, {%0,%1,%2,%3};"
                        : "+f"(c[0]), "+f"(c[1]), "+f"(c[2]), "+f"(c[3])
                        : "r"(a[mi][0]), "r"(a[mi][1]), "r"(a[mi][2]), "r"(a[mi][3]),
                          "r"(b[ni][0]), "r"(b[ni][1]));
                }
        }
    }

    // Epilogue: store fp32 pre-activations
    size_t baseM = (size_t)mtile * BM + wm * 64;
    size_t baseN = (size_t)ntile * BN + wn * 64;
#pragma unroll
    for (int mi = 0; mi < 4; mi++)
#pragma unroll
        for (int ni = 0; ni < 8; ni++) {
            size_t r = baseM + mi * 16 + rq;
            size_t cc = baseN + ni * 8 + cq * 2;
            *reinterpret_cast<float2*>(g_pre + r * Nn + cc) =
                make_float2(acc[mi][ni][0], acc[mi][ni][1]);
            *reinterpret_cast<float2*>(g_pre + (r + 8) * Nn + cc) =
                make_float2(acc[mi][ni][2], acc[mi][ni][3]);
        }
}

// ---------------------------------------------------------------------------
// Elementwise LSTM gate update (float4)
// ---------------------------------------------------------------------------
__device__ __forceinline__ float sigm(float x) { return 1.f / (1.f + __expf(-x)); }
__device__ __forceinline__ float tanh_f(float x) { return 2.f * sigm(2.f * x) - 1.f; }

__global__ void lstm_elem(const float* __restrict__ c, const float* __restrict__ bi,
                          float* __restrict__ out, int out_size) {
    int i4 = blockIdx.x * blockDim.x + threadIdx.x;  // float4 index
    int b = i4 >> 8, h4 = i4 & 255;
    const float4* p  = reinterpret_cast<const float4*>(g_pre + (size_t)b * Nn);
    const float4* b4 = reinterpret_cast<const float4*>(bi);

    float4 pi = p[h4],       vb0 = b4[h4];
    float4 pf = p[256 + h4], vb1 = b4[256 + h4];
    float4 pg = p[512 + h4], vb2 = b4[512 + h4];
    float4 po = p[768 + h4], vb3 = b4[768 + h4];
    float4 cv = reinterpret_cast<const float4*>(c)[i4];

    float4 go, nh, nc;
    {
        float gi, gf, gg, gO, t;
#define LANE(W)                                                         \
        gi = sigm(pi.W + vb0.W); gf = sigm(pf.W + vb1.W);               \
        gg = tanh_f(pg.W + vb2.W); gO = sigm(po.W + vb3.W);             \
        nc.W = gf * cv.W + gi * gg; t = tanh_f(nc.W);                   \
        nh.W = gO * t; go.W = gO;
        LANE(x) LANE(y) LANE(z) LANE(w)
#undef LANE
    }

    float4* o4 = reinterpret_cast<float4*>(out);
    o4[i4] = go;
    if (out_size >= 3 * Bb * Hh) {
        o4[(Bb * Hh / 4) + i4]     = nh;
        o4[(2 * Bb * Hh / 4) + i4] = nc;
    }
}

// ---------------------------------------------------------------------------
// Launch: pack -> GEMM -> elementwise (graph-capturable)
// ---------------------------------------------------------------------------
extern "C" void kernel_launch(void* const* d_in, const int* in_sizes, int n_in,
                              void* d_out, int out_size) {
    const float* x  = (const float*)d_in[0];
    const float* h  = (const float*)d_in[1];
    const float* c  = (const float*)d_in[2];
    const float* Wi = (const float*)d_in[3];
    const float* bi = (const float*)d_in[4];
    const float* Wh = (const float*)d_in[5];
    float* out = (float*)d_out;

    pack_A<<<32768, 256>>>(x, h);
    pack_W<<<8192, 256>>>(Wi, Wh);

    cudaFuncSetAttribute(gemm_tf32, cudaFuncAttributeMaxDynamicSharedMemorySize,
                         GEMM_SMEM_BYTES);
    gemm_tf32<<<(Bb / BM) * (Nn / BN), 256, GEMM_SMEM_BYTES>>>();  // 2048 CTAs

    lstm_elem<<<(Bb * Hh / 4) / 256, 256>>>(c, bi, out, out_size);
}